// round 4
// baseline (speedup 1.0000x reference)
#include <cuda_runtime.h>
#include <math.h>

#define BB 8
#define TT 2048
#define CC 1024
#define HH 64

#define ATTN_CTAS 304
#define SMEM_FLOATS 13312

// scratch for q,k,v projections (B*T*H floats each = 4 MB each)
__device__ float g_q[BB*TT*HH];
__device__ float g_k[BB*TT*HH];
__device__ float g_v[BB*TT*HH];
__device__ int   g_ctr  = 0;
__device__ int   g_done = 0;

typedef unsigned long long u64;

// ---- packed fp32x2 helpers (FFMA2 path; ptxas never auto-fuses this) ----
__device__ __forceinline__ u64 pack2(float x, float y) {
    u64 r; asm("mov.b64 %0, {%1, %2};" : "=l"(r) : "f"(x), "f"(y)); return r;
}
__device__ __forceinline__ void unpack2(u64 v, float& x, float& y) {
    asm("mov.b64 {%0, %1}, %2;" : "=f"(x), "=f"(y) : "l"(v));
}
__device__ __forceinline__ void ffma2(u64& d, u64 a, u64 b) {
    asm("fma.rn.f32x2 %0, %1, %2, %0;" : "+l"(d) : "l"(a), "l"(b));
}
__device__ __forceinline__ u64 mul2(u64 a, u64 b) {
    u64 r; asm("mul.rn.f32x2 %0, %1, %2;" : "=l"(r) : "l"(a), "l"(b)); return r;
}

// ---------------------------------------------------------------------------
// Kernel 1: fused QKV projection.  out[b,t,h] = sum_c x[b,t,c] * W[c,h]
// Grid: (256, 3) ; block 256.  Each block: 64 rows x 64 cols output tile.
// Accumulators are f32x2 pairs along the h (col) axis.
// ---------------------------------------------------------------------------
__global__ __launch_bounds__(256) void proj_kernel(
    const float* __restrict__ x,
    const float* __restrict__ Wq,
    const float* __restrict__ Wk,
    const float* __restrict__ Wv)
{
    __shared__ float sX[64][68];   // [c][m]  (x tile transposed)
    __shared__ float sW[64][68];   // [c][h]

    const int tid  = threadIdx.x;
    const int row0 = blockIdx.x * 64;
    const int ty   = tid >> 4;     // 0..15 -> 4 rows each
    const int tx   = tid & 15;     // 0..15 -> 4 cols each

    const float* W;
    float* out;
    if (blockIdx.y == 0)      { W = Wq; out = g_q; }
    else if (blockIdx.y == 1) { W = Wk; out = g_k; }
    else                      { W = Wv; out = g_v; }

    u64 acc2[4][2];
    #pragma unroll
    for (int i = 0; i < 4; i++) { acc2[i][0] = 0ull; acc2[i][1] = 0ull; }

    for (int c0 = 0; c0 < CC; c0 += 64) {
        #pragma unroll
        for (int i = 0; i < 4; i++) {
            int e  = tid + i * 256;
            int m  = e >> 4;
            int c4 = (e & 15) * 4;
            float4 v = *(const float4*)&x[(size_t)(row0 + m) * CC + c0 + c4];
            sX[c4 + 0][m] = v.x;
            sX[c4 + 1][m] = v.y;
            sX[c4 + 2][m] = v.z;
            sX[c4 + 3][m] = v.w;
        }
        #pragma unroll
        for (int i = 0; i < 4; i++) {
            int e  = tid + i * 256;
            int c  = e >> 4;
            int h4 = (e & 15) * 4;
            *(float4*)&sW[c][h4] = *(const float4*)&W[(size_t)(c0 + c) * HH + h4];
        }
        __syncthreads();

        #pragma unroll 8
        for (int c = 0; c < 64; c++) {
            float4 a  = *(float4*)&sX[c][ty * 4];
            float4 bv = *(float4*)&sW[c][tx * 4];
            u64 b01 = pack2(bv.x, bv.y);
            u64 b23 = pack2(bv.z, bv.w);
            u64 a0 = pack2(a.x, a.x);
            u64 a1 = pack2(a.y, a.y);
            u64 a2 = pack2(a.z, a.z);
            u64 a3 = pack2(a.w, a.w);
            ffma2(acc2[0][0], a0, b01); ffma2(acc2[0][1], a0, b23);
            ffma2(acc2[1][0], a1, b01); ffma2(acc2[1][1], a1, b23);
            ffma2(acc2[2][0], a2, b01); ffma2(acc2[2][1], a2, b23);
            ffma2(acc2[3][0], a3, b01); ffma2(acc2[3][1], a3, b23);
        }
        __syncthreads();
    }

    #pragma unroll
    for (int i = 0; i < 4; i++) {
        float4 o;
        unpack2(acc2[i][0], o.x, o.y);
        unpack2(acc2[i][1], o.z, o.w);
        *(float4*)&out[(size_t)(row0 + ty * 4 + i) * HH + tx * 4] = o;
    }
}

// ---------------------------------------------------------------------------
// Kernel 2: persistent causal flash attention with work stealing.
// Grid: 304 CTAs (2/SM on 152 SMs), block 256.  Job = (batch, 32-row q-tile);
// 512 jobs pulled heavy-first from g_ctr.  BN=64 kv per chunk.
// Accumulators are f32x2 pairs along the query-row axis (rows r, r+1), which
// load directly as 8-byte LDS from the [.][m]-transposed smem tiles.
// Dynamic smem layout (floats):
//   sQ [64][36]  @0       sK [64][68] @2304   sV [64][68] @6656   sP [64][36] @11008
// total 13312 floats = 53248 B
// ---------------------------------------------------------------------------
__global__ __launch_bounds__(256) void attn_kernel(float* __restrict__ out)
{
    extern __shared__ float sm[];
    float* sQ = sm;             // stride 36
    float* sK = sm + 2304;      // stride 68
    float* sV = sm + 6656;      // stride 68
    float* sP = sm + 11008;     // stride 36

    __shared__ int sJob;

    const int tid = threadIdx.x;
    const int ty  = tid >> 4;      // 0..15 -> 2 rows each
    const int tx  = tid & 15;      // 0..15 -> 4 cols each
    const int r   = ty * 2;

    for (;;) {
        if (tid == 0) sJob = atomicAdd(&g_ctr, 1);
        __syncthreads();           // also: previous job's smem reads are done
        const int job = sJob;
        if (job >= 512) break;

        const int qt = 63 - (job >> 3);    // heavy jobs first
        const int b  = job & 7;
        const int q0 = qt * 32;

        const float* q = g_q + (size_t)b * TT * HH;
        const float* k = g_k + (size_t)b * TT * HH;
        const float* v = g_v + (size_t)b * TT * HH;

        // load Q tile 32(m) x 64(h), transposed & pre-scaled by 1/sqrt(H)
        #pragma unroll
        for (int i = 0; i < 2; i++) {
            int e  = tid + i * 256;
            int m  = e >> 4;
            int h4 = (e & 15) * 4;
            float4 val = *(const float4*)&q[(size_t)(q0 + m) * HH + h4];
            sQ[(h4 + 0) * 36 + m] = val.x * 0.125f;
            sQ[(h4 + 1) * 36 + m] = val.y * 0.125f;
            sQ[(h4 + 2) * 36 + m] = val.z * 0.125f;
            sQ[(h4 + 3) * 36 + m] = val.w * 0.125f;
        }

        float m_i[2] = {-INFINITY, -INFINITY};
        float l_i[2] = {0.f, 0.f};
        u64 acc2[4] = {0ull, 0ull, 0ull, 0ull};   // [col j] packs rows (r, r+1)

        const int n_chunks = (qt + 2) >> 1;   // ceil((qt+1)/2)
        for (int t = 0; t < n_chunks; t++) {
            const int kv0 = t * 64;
            __syncthreads();   // previous chunk's sK/sV/sP readers done

            // load K tile 64(n) x 64(h) transposed -> sK[h][n]
            #pragma unroll
            for (int i = 0; i < 4; i++) {
                int e  = tid + i * 256;
                int n  = e >> 4;
                int h4 = (e & 15) * 4;
                float4 val = *(const float4*)&k[(size_t)(kv0 + n) * HH + h4];
                sK[(h4 + 0) * 68 + n] = val.x;
                sK[(h4 + 1) * 68 + n] = val.y;
                sK[(h4 + 2) * 68 + n] = val.z;
                sK[(h4 + 3) * 68 + n] = val.w;
            }
            // load V tile 64(n) x 64(h) natural -> sV[n][h]
            #pragma unroll
            for (int i = 0; i < 4; i++) {
                int e  = tid + i * 256;
                int n  = e >> 4;
                int h4 = (e & 15) * 4;
                *(float4*)&sV[n * 68 + h4] =
                    *(const float4*)&v[(size_t)(kv0 + n) * HH + h4];
            }
            __syncthreads();   // K/V (and Q on first chunk) visible

            // S = Q K^T : row-pair (r,r+1) x 4 cols per thread, packed f32x2
            u64 s2[4] = {0ull, 0ull, 0ull, 0ull};
            #pragma unroll 8
            for (int h = 0; h < 64; h++) {
                u64 a = *(const u64*)&sQ[h * 36 + r];          // (row r, row r+1)
                float4 bb = *(float4*)&sK[h * 68 + tx * 4];
                ffma2(s2[0], a, pack2(bb.x, bb.x));
                ffma2(s2[1], a, pack2(bb.y, bb.y));
                ffma2(s2[2], a, pack2(bb.z, bb.z));
                ffma2(s2[3], a, pack2(bb.w, bb.w));
            }
            float s[2][4];
            #pragma unroll
            for (int j = 0; j < 4; j++) unpack2(s2[j], s[0][j], s[1][j]);

            // causal mask (chunks touching the diagonal band)
            if (kv0 + 64 > q0) {
                #pragma unroll
                for (int i = 0; i < 2; i++) {
                    int qr = q0 + r + i;
                    #pragma unroll
                    for (int j = 0; j < 4; j++) {
                        if (kv0 + tx * 4 + j > qr) s[i][j] = -INFINITY;
                    }
                }
            }

            // online softmax; row owned by 16 lanes (shfl width 16)
            float alpha[2];
            #pragma unroll
            for (int i = 0; i < 2; i++) {
                float mx = fmaxf(fmaxf(s[i][0], s[i][1]), fmaxf(s[i][2], s[i][3]));
                #pragma unroll
                for (int off = 8; off >= 1; off >>= 1)
                    mx = fmaxf(mx, __shfl_xor_sync(0xffffffffu, mx, off));
                float m_new = fmaxf(m_i[i], mx);
                alpha[i] = __expf(m_i[i] - m_new);
                float p0 = __expf(s[i][0] - m_new);
                float p1 = __expf(s[i][1] - m_new);
                float p2 = __expf(s[i][2] - m_new);
                float p3 = __expf(s[i][3] - m_new);
                float rs = (p0 + p1) + (p2 + p3);
                #pragma unroll
                for (int off = 8; off >= 1; off >>= 1)
                    rs += __shfl_xor_sync(0xffffffffu, rs, off);
                l_i[i] = l_i[i] * alpha[i] + rs;
                m_i[i] = m_new;
                s[i][0] = p0; s[i][1] = p1; s[i][2] = p2; s[i][3] = p3;
            }
            // rescale O accumulators (packed: different alpha per row lane)
            {
                u64 am = pack2(alpha[0], alpha[1]);
                #pragma unroll
                for (int j = 0; j < 4; j++) acc2[j] = mul2(acc2[j], am);
            }

            // store P transposed -> sP[n][m]
            #pragma unroll
            for (int j = 0; j < 4; j++) {
                sP[(tx * 4 + j) * 36 + r + 0] = s[0][j];
                sP[(tx * 4 + j) * 36 + r + 1] = s[1][j];
            }
            __syncthreads();   // sP complete

            // O += P * V : packed row-pair x 4 h-cols, inner over 64 kv
            #pragma unroll 8
            for (int n = 0; n < 64; n++) {
                u64 a = *(const u64*)&sP[n * 36 + r];           // (row r, row r+1)
                float4 bb = *(float4*)&sV[n * 68 + tx * 4];
                ffma2(acc2[0], a, pack2(bb.x, bb.x));
                ffma2(acc2[1], a, pack2(bb.y, bb.y));
                ffma2(acc2[2], a, pack2(bb.z, bb.z));
                ffma2(acc2[3], a, pack2(bb.w, bb.w));
            }
        }

        // epilogue: normalize and write
        float o0[4], o1[4];
        #pragma unroll
        for (int j = 0; j < 4; j++) unpack2(acc2[j], o0[j], o1[j]);
        {
            float inv0 = 1.f / l_i[0];
            float4 o = make_float4(o0[0] * inv0, o0[1] * inv0, o0[2] * inv0, o0[3] * inv0);
            *(float4*)&out[((size_t)b * TT + q0 + r + 0) * HH + tx * 4] = o;
        }
        {
            float inv1 = 1.f / l_i[1];
            float4 o = make_float4(o1[0] * inv1, o1[1] * inv1, o1[2] * inv1, o1[3] * inv1);
            *(float4*)&out[((size_t)b * TT + q0 + r + 1) * HH + tx * 4] = o;
        }
    }

    // last CTA out resets the work counter for the next (graph-replayed) launch
    if (tid == 0) {
        if (atomicAdd(&g_done, 1) == ATTN_CTAS - 1) {
            g_ctr  = 0;
            g_done = 0;
        }
    }
}

extern "C" void kernel_launch(void* const* d_in, const int* in_sizes, int n_in,
                              void* d_out, int out_size)
{
    const float* x  = (const float*)d_in[0];
    const float* Wq = (const float*)d_in[1];
    const float* Wk = (const float*)d_in[2];
    const float* Wv = (const float*)d_in[3];
    float* out = (float*)d_out;

    cudaFuncSetAttribute(attn_kernel,
                         cudaFuncAttributeMaxDynamicSharedMemorySize,
                         SMEM_FLOATS * (int)sizeof(float));

    proj_kernel<<<dim3(BB * TT / 64, 3), 256>>>(x, Wq, Wk, Wv);
    attn_kernel<<<ATTN_CTAS, 256, SMEM_FLOATS * sizeof(float)>>>(out);
}

// round 6
// speedup vs baseline: 1.5217x; 1.5217x over previous
#include <cuda_runtime.h>
#include <cuda_bf16.h>
#include <math.h>
#include <cstdint>

#define BB 8
#define TT 2048
#define CC 1024
#define HH 64

#define ATTN_CTAS 304
#define ATTN_SMEM_FLOATS 13312

// scratch
__device__ float g_q[BB*TT*HH];
__device__ float g_k[BB*TT*HH];
__device__ float g_v[BB*TT*HH];
__device__ __nv_bfloat16 g_wt_hi[192*CC];   // W^T [n][k]: n = mat*64+h
__device__ __nv_bfloat16 g_wt_lo[192*CC];
__device__ int g_ctr  = 0;
__device__ int g_done = 0;

// ---- mma.sync m16n8k16 bf16 (baseline sm_80+ instruction; safe on sm_103) --
__device__ __forceinline__ void mma16816(float* c, const uint32_t* a, const uint32_t* b) {
    asm volatile(
        "mma.sync.aligned.m16n8k16.row.col.f32.bf16.bf16.f32 "
        "{%0,%1,%2,%3}, {%4,%5,%6,%7}, {%8,%9}, {%0,%1,%2,%3};"
        : "+f"(c[0]), "+f"(c[1]), "+f"(c[2]), "+f"(c[3])
        : "r"(a[0]), "r"(a[1]), "r"(a[2]), "r"(a[3]), "r"(b[0]), "r"(b[1]));
}

// ---------------------------------------------------------------------------
// Prep: W^T hi/lo bf16.  wt[n][k], n = mat*64 + h, value Wmat[k][h].
// ---------------------------------------------------------------------------
__global__ __launch_bounds__(256) void wprep_kernel(
    const float* __restrict__ Wq, const float* __restrict__ Wk,
    const float* __restrict__ Wv)
{
    int n = blockIdx.x;                 // 0..191
    const float* W = (n < 64) ? Wq : (n < 128) ? Wk : Wv;
    int h = n & 63;
    for (int k = threadIdx.x; k < CC; k += 256) {
        float v = W[(size_t)k * HH + h];
        __nv_bfloat16 hi = __float2bfloat16(v);
        __nv_bfloat16 lo = __float2bfloat16(v - __bfloat162float(hi));
        g_wt_hi[(size_t)n * CC + k] = hi;
        g_wt_lo[(size_t)n * CC + k] = lo;
    }
}

// ---------------------------------------------------------------------------
// Projection GEMM on tensor cores (mma.sync bf16, hi/lo split).
// Grid: 128 CTAs (one 128-row M tile each), 256 threads = 8 warps (4M x 2N).
// N = 192 (Q|K|V).  K chunks of 32.
// Dynamic smem (bf16 units, row stride 40 = 80B, bank-conflict-free):
//   sAh @0      [128][40]   sAl @5120  [128][40]
//   sBh @10240  [192][40]   sBl @17920 [192][40]
// total 25600 bf16 = 51200 B
// ---------------------------------------------------------------------------
#define PROJ_SMEM 51200

__global__ __launch_bounds__(256, 1) void proj_mma_kernel(const float* __restrict__ x)
{
    extern __shared__ __nv_bfloat16 sb[];
    __nv_bfloat16* sAh = sb;
    __nv_bfloat16* sAl = sb + 5120;
    __nv_bfloat16* sBh = sb + 10240;
    __nv_bfloat16* sBl = sb + 17920;

    const int tid  = threadIdx.x;
    const int wid  = tid >> 5;
    const int lane = tid & 31;
    const int g    = lane >> 2;      // groupID 0..7
    const int tg   = lane & 3;       // thread-in-group 0..3
    const int m0   = blockIdx.x * 128;
    const int m0w  = (wid >> 1) * 32;   // warp M offset (0,32,64,96)
    const int n0w  = (wid & 1) * 96;    // warp N offset (0,96)

    float acc[2][12][4];
    #pragma unroll
    for (int mt = 0; mt < 2; mt++)
        #pragma unroll
        for (int nt = 0; nt < 12; nt++)
            #pragma unroll
            for (int i = 0; i < 4; i++) acc[mt][nt][i] = 0.f;

    for (int kc = 0; kc < 32; kc++) {
        const int k0 = kc * 32;

        // ---- load x tile 128 x 32 fp32 -> hi/lo bf16 ----
        #pragma unroll
        for (int t = 0; t < 4; t++) {
            int e   = tid + t * 256;
            int row = e >> 3;
            int q   = e & 7;
            float4 v = *(const float4*)&x[(size_t)(m0 + row) * CC + k0 + q * 4];
            __nv_bfloat16 hx = __float2bfloat16(v.x), hy = __float2bfloat16(v.y);
            __nv_bfloat16 hz = __float2bfloat16(v.z), hw = __float2bfloat16(v.w);
            uint2 hv, lv;
            hv.x = ((uint32_t)__bfloat16_as_ushort(hy) << 16) | __bfloat16_as_ushort(hx);
            hv.y = ((uint32_t)__bfloat16_as_ushort(hw) << 16) | __bfloat16_as_ushort(hz);
            __nv_bfloat162 l01 = __floats2bfloat162_rn(v.x - __bfloat162float(hx),
                                                       v.y - __bfloat162float(hy));
            __nv_bfloat162 l23 = __floats2bfloat162_rn(v.z - __bfloat162float(hz),
                                                       v.w - __bfloat162float(hw));
            lv.x = *reinterpret_cast<uint32_t*>(&l01);
            lv.y = *reinterpret_cast<uint32_t*>(&l23);
            *(uint2*)&sAh[row * 40 + q * 4] = hv;
            *(uint2*)&sAl[row * 40 + q * 4] = lv;
        }
        // ---- load W^T tiles 192 x 32 bf16 (pre-split) ----
        #pragma unroll
        for (int t = 0; t < 6; t++) {
            int e = tid + t * 256;
            int n = e >> 3;
            int q = e & 7;
            *(uint2*)&sBh[n * 40 + q * 4] =
                *(const uint2*)&g_wt_hi[(size_t)n * CC + k0 + q * 4];
            *(uint2*)&sBl[n * 40 + q * 4] =
                *(const uint2*)&g_wt_lo[(size_t)n * CC + k0 + q * 4];
        }
        __syncthreads();

        #pragma unroll
        for (int ks = 0; ks < 32; ks += 16) {
            // A fragments (hi & lo), 2 m-tiles
            uint32_t ah[2][4], al[2][4];
            #pragma unroll
            for (int mt = 0; mt < 2; mt++) {
                int r0 = (m0w + mt * 16 + g) * 40 + ks + tg * 2;
                int r1 = r0 + 8 * 40;
                ah[mt][0] = *(const uint32_t*)&sAh[r0];
                ah[mt][1] = *(const uint32_t*)&sAh[r1];
                ah[mt][2] = *(const uint32_t*)&sAh[r0 + 8];
                ah[mt][3] = *(const uint32_t*)&sAh[r1 + 8];
                al[mt][0] = *(const uint32_t*)&sAl[r0];
                al[mt][1] = *(const uint32_t*)&sAl[r1];
                al[mt][2] = *(const uint32_t*)&sAl[r0 + 8];
                al[mt][3] = *(const uint32_t*)&sAl[r1 + 8];
            }
            #pragma unroll
            for (int nt = 0; nt < 12; nt++) {
                int rb = (n0w + nt * 8 + g) * 40 + ks + tg * 2;
                uint32_t bh[2], bl[2];
                bh[0] = *(const uint32_t*)&sBh[rb];
                bh[1] = *(const uint32_t*)&sBh[rb + 8];
                bl[0] = *(const uint32_t*)&sBl[rb];
                bl[1] = *(const uint32_t*)&sBl[rb + 8];
                #pragma unroll
                for (int mt = 0; mt < 2; mt++) {
                    mma16816(acc[mt][nt], ah[mt], bh);
                    mma16816(acc[mt][nt], ah[mt], bl);
                    mma16816(acc[mt][nt], al[mt], bh);
                }
            }
        }
        __syncthreads();
    }

    // epilogue: fragment -> g_q / g_k / g_v
    #pragma unroll
    for (int nt = 0; nt < 12; nt++) {
        int nbase = n0w + nt * 8;
        float* dst = (nbase < 64) ? g_q : (nbase < 128) ? g_k : g_v;
        int h = (nbase & 63) + tg * 2;
        #pragma unroll
        for (int mt = 0; mt < 2; mt++) {
            int row0 = m0 + m0w + mt * 16 + g;
            float2 c01 = make_float2(acc[mt][nt][0], acc[mt][nt][1]);
            float2 c23 = make_float2(acc[mt][nt][2], acc[mt][nt][3]);
            *(float2*)&dst[(size_t)row0 * HH + h]       = c01;
            *(float2*)&dst[(size_t)(row0 + 8) * HH + h] = c23;
        }
    }
}

// ---------------------------------------------------------------------------
// Persistent causal flash attention (scalar fp32, R3 version), 304 CTAs.
// ---------------------------------------------------------------------------
__global__ __launch_bounds__(256) void attn_kernel(float* __restrict__ out)
{
    extern __shared__ float sm[];
    float* sQ = sm;             // stride 36
    float* sK = sm + 2304;      // stride 68
    float* sV = sm + 6656;      // stride 68
    float* sP = sm + 11008;     // stride 36

    __shared__ int sJob;

    const int tid = threadIdx.x;
    const int ty  = tid >> 4;
    const int tx  = tid & 15;
    const int r   = ty * 2;

    for (;;) {
        if (tid == 0) sJob = atomicAdd(&g_ctr, 1);
        __syncthreads();
        const int job = sJob;
        if (job >= 512) break;

        const int qt = 63 - (job >> 3);
        const int b  = job & 7;
        const int q0 = qt * 32;

        const float* q = g_q + (size_t)b * TT * HH;
        const float* k = g_k + (size_t)b * TT * HH;
        const float* v = g_v + (size_t)b * TT * HH;

        #pragma unroll
        for (int i = 0; i < 2; i++) {
            int e  = tid + i * 256;
            int m  = e >> 4;
            int h4 = (e & 15) * 4;
            float4 val = *(const float4*)&q[(size_t)(q0 + m) * HH + h4];
            sQ[(h4 + 0) * 36 + m] = val.x * 0.125f;
            sQ[(h4 + 1) * 36 + m] = val.y * 0.125f;
            sQ[(h4 + 2) * 36 + m] = val.z * 0.125f;
            sQ[(h4 + 3) * 36 + m] = val.w * 0.125f;
        }

        float m_i[2] = {-INFINITY, -INFINITY};
        float l_i[2] = {0.f, 0.f};
        float acc[2][4];
        #pragma unroll
        for (int i = 0; i < 2; i++)
            #pragma unroll
            for (int j = 0; j < 4; j++) acc[i][j] = 0.f;

        const int n_chunks = (qt + 2) >> 1;
        for (int t = 0; t < n_chunks; t++) {
            const int kv0 = t * 64;
            __syncthreads();

            #pragma unroll
            for (int i = 0; i < 4; i++) {
                int e  = tid + i * 256;
                int n  = e >> 4;
                int h4 = (e & 15) * 4;
                float4 val = *(const float4*)&k[(size_t)(kv0 + n) * HH + h4];
                sK[(h4 + 0) * 68 + n] = val.x;
                sK[(h4 + 1) * 68 + n] = val.y;
                sK[(h4 + 2) * 68 + n] = val.z;
                sK[(h4 + 3) * 68 + n] = val.w;
            }
            #pragma unroll
            for (int i = 0; i < 4; i++) {
                int e  = tid + i * 256;
                int n  = e >> 4;
                int h4 = (e & 15) * 4;
                *(float4*)&sV[n * 68 + h4] =
                    *(const float4*)&v[(size_t)(kv0 + n) * HH + h4];
            }
            __syncthreads();

            float s[2][4];
            #pragma unroll
            for (int j = 0; j < 4; j++) { s[0][j] = 0.f; s[1][j] = 0.f; }
            #pragma unroll 8
            for (int h = 0; h < 64; h++) {
                float2 a  = *(float2*)&sQ[h * 36 + r];
                float4 bb = *(float4*)&sK[h * 68 + tx * 4];
                s[0][0] += a.x * bb.x;  s[0][1] += a.x * bb.y;
                s[0][2] += a.x * bb.z;  s[0][3] += a.x * bb.w;
                s[1][0] += a.y * bb.x;  s[1][1] += a.y * bb.y;
                s[1][2] += a.y * bb.z;  s[1][3] += a.y * bb.w;
            }

            if (kv0 + 64 > q0) {
                #pragma unroll
                for (int i = 0; i < 2; i++) {
                    int qr = q0 + r + i;
                    #pragma unroll
                    for (int j = 0; j < 4; j++) {
                        if (kv0 + tx * 4 + j > qr) s[i][j] = -INFINITY;
                    }
                }
            }

            #pragma unroll
            for (int i = 0; i < 2; i++) {
                float mx = fmaxf(fmaxf(s[i][0], s[i][1]), fmaxf(s[i][2], s[i][3]));
                #pragma unroll
                for (int off = 8; off >= 1; off >>= 1)
                    mx = fmaxf(mx, __shfl_xor_sync(0xffffffffu, mx, off));
                float m_new = fmaxf(m_i[i], mx);
                float alpha = __expf(m_i[i] - m_new);
                float p0 = __expf(s[i][0] - m_new);
                float p1 = __expf(s[i][1] - m_new);
                float p2 = __expf(s[i][2] - m_new);
                float p3 = __expf(s[i][3] - m_new);
                float rs = (p0 + p1) + (p2 + p3);
                #pragma unroll
                for (int off = 8; off >= 1; off >>= 1)
                    rs += __shfl_xor_sync(0xffffffffu, rs, off);
                l_i[i] = l_i[i] * alpha + rs;
                m_i[i] = m_new;
                s[i][0] = p0; s[i][1] = p1; s[i][2] = p2; s[i][3] = p3;
                #pragma unroll
                for (int j = 0; j < 4; j++) acc[i][j] *= alpha;
            }

            #pragma unroll
            for (int j = 0; j < 4; j++) {
                sP[(tx * 4 + j) * 36 + r + 0] = s[0][j];
                sP[(tx * 4 + j) * 36 + r + 1] = s[1][j];
            }
            __syncthreads();

            #pragma unroll 8
            for (int n = 0; n < 64; n++) {
                float2 a  = *(float2*)&sP[n * 36 + r];
                float4 bb = *(float4*)&sV[n * 68 + tx * 4];
                acc[0][0] += a.x * bb.x; acc[0][1] += a.x * bb.y;
                acc[0][2] += a.x * bb.z; acc[0][3] += a.x * bb.w;
                acc[1][0] += a.y * bb.x; acc[1][1] += a.y * bb.y;
                acc[1][2] += a.y * bb.z; acc[1][3] += a.y * bb.w;
            }
        }

        #pragma unroll
        for (int i = 0; i < 2; i++) {
            float inv = 1.f / l_i[i];
            float4 o = make_float4(acc[i][0] * inv, acc[i][1] * inv,
                                   acc[i][2] * inv, acc[i][3] * inv);
            *(float4*)&out[((size_t)b * TT + q0 + r + i) * HH + tx * 4] = o;
        }
    }

    if (tid == 0) {
        if (atomicAdd(&g_done, 1) == ATTN_CTAS - 1) {
            g_ctr  = 0;
            g_done = 0;
        }
    }
}

extern "C" void kernel_launch(void* const* d_in, const int* in_sizes, int n_in,
                              void* d_out, int out_size)
{
    const float* x  = (const float*)d_in[0];
    const float* Wq = (const float*)d_in[1];
    const float* Wk = (const float*)d_in[2];
    const float* Wv = (const float*)d_in[3];
    float* out = (float*)d_out;

    cudaFuncSetAttribute(proj_mma_kernel,
                         cudaFuncAttributeMaxDynamicSharedMemorySize, PROJ_SMEM);
    cudaFuncSetAttribute(attn_kernel,
                         cudaFuncAttributeMaxDynamicSharedMemorySize,
                         ATTN_SMEM_FLOATS * (int)sizeof(float));

    wprep_kernel<<<192, 256>>>(Wq, Wk, Wv);
    proj_mma_kernel<<<BB * TT / 128, 256, PROJ_SMEM>>>(x);
    attn_kernel<<<ATTN_CTAS, 256, ATTN_SMEM_FLOATS * sizeof(float)>>>(out);
}

// round 7
// speedup vs baseline: 2.6364x; 1.7325x over previous
#include <cuda_runtime.h>
#include <cuda_bf16.h>
#include <math.h>
#include <cstdint>

#define BB 8
#define TT 2048
#define CC 1024
#define HH 64

// bf16 hi/lo tensors produced by the projection
__device__ __nv_bfloat16 g_qh[BB*TT*HH], g_ql[BB*TT*HH];   // [b][t][h], pre-scaled
__device__ __nv_bfloat16 g_kh[BB*TT*HH], g_kl[BB*TT*HH];   // [b][t][h]
__device__ __nv_bfloat16 g_vth[BB*HH*TT], g_vtl[BB*HH*TT]; // [b][h][t]  (transposed!)
__device__ __nv_bfloat16 g_wt_hi[192*CC];                  // W^T [n][k]: n = mat*64+h
__device__ __nv_bfloat16 g_wt_lo[192*CC];
__device__ int g_ctr  = 0;
__device__ int g_done = 0;

// ---- mma.sync m16n8k16 bf16 (sm_80 baseline; compiles for plain sm_103) ----
__device__ __forceinline__ void mma16816(float* c, const uint32_t* a, const uint32_t* b) {
    asm volatile(
        "mma.sync.aligned.m16n8k16.row.col.f32.bf16.bf16.f32 "
        "{%0,%1,%2,%3}, {%4,%5,%6,%7}, {%8,%9}, {%0,%1,%2,%3};"
        : "+f"(c[0]), "+f"(c[1]), "+f"(c[2]), "+f"(c[3])
        : "r"(a[0]), "r"(a[1]), "r"(a[2]), "r"(a[3]), "r"(b[0]), "r"(b[1]));
}

__device__ __forceinline__ uint32_t hi2(float a, float b) {
    return ((uint32_t)__bfloat16_as_ushort(__float2bfloat16(b)) << 16) |
           (uint32_t)__bfloat16_as_ushort(__float2bfloat16(a));
}
__device__ __forceinline__ uint32_t lo2(float a, float b) {
    float ra = a - __bfloat162float(__float2bfloat16(a));
    float rb = b - __bfloat162float(__float2bfloat16(b));
    return hi2(ra, rb);
}

// ---------------------------------------------------------------------------
// Prep: W^T hi/lo bf16.  wt[n][k], n = mat*64 + h, value Wmat[k][h].
// ---------------------------------------------------------------------------
__global__ __launch_bounds__(256) void wprep_kernel(
    const float* __restrict__ Wq, const float* __restrict__ Wk,
    const float* __restrict__ Wv)
{
    int n = blockIdx.x;                 // 0..191
    const float* W = (n < 64) ? Wq : (n < 128) ? Wk : Wv;
    int h = n & 63;
    for (int k = threadIdx.x; k < CC; k += 256) {
        float v = W[(size_t)k * HH + h];
        __nv_bfloat16 hi = __float2bfloat16(v);
        __nv_bfloat16 lo = __float2bfloat16(v - __bfloat162float(hi));
        g_wt_hi[(size_t)n * CC + k] = hi;
        g_wt_lo[(size_t)n * CC + k] = lo;
    }
}

// ---------------------------------------------------------------------------
// Projection GEMM (mma.sync bf16 hi/lo).  128 CTAs x 256 thr (8 warps 4Mx2N).
// Epilogue: Q (x0.125), K -> bf16 hi/lo [t][h];  V -> smem transpose -> [h][t].
// smem: main loop 51200 B; epilogue reuses it for the V transpose staging.
// ---------------------------------------------------------------------------
#define PROJ_SMEM 51200

__global__ __launch_bounds__(256, 1) void proj_mma_kernel(const float* __restrict__ x)
{
    extern __shared__ __nv_bfloat16 sb[];
    __nv_bfloat16* sAh = sb;
    __nv_bfloat16* sAl = sb + 5120;
    __nv_bfloat16* sBh = sb + 10240;
    __nv_bfloat16* sBl = sb + 17920;

    const int tid  = threadIdx.x;
    const int wid  = tid >> 5;
    const int lane = tid & 31;
    const int g    = lane >> 2;
    const int tg   = lane & 3;
    const int m0   = blockIdx.x * 128;
    const int m0w  = (wid >> 1) * 32;
    const int n0w  = (wid & 1) * 96;

    float acc[2][12][4];
    #pragma unroll
    for (int mt = 0; mt < 2; mt++)
        #pragma unroll
        for (int nt = 0; nt < 12; nt++)
            #pragma unroll
            for (int i = 0; i < 4; i++) acc[mt][nt][i] = 0.f;

    for (int kc = 0; kc < 32; kc++) {
        const int k0 = kc * 32;
        #pragma unroll
        for (int t = 0; t < 4; t++) {
            int e   = tid + t * 256;
            int row = e >> 3;
            int q   = e & 7;
            float4 v = *(const float4*)&x[(size_t)(m0 + row) * CC + k0 + q * 4];
            uint2 hv, lv;
            hv.x = hi2(v.x, v.y);  hv.y = hi2(v.z, v.w);
            lv.x = lo2(v.x, v.y);  lv.y = lo2(v.z, v.w);
            *(uint2*)&sAh[row * 40 + q * 4] = hv;
            *(uint2*)&sAl[row * 40 + q * 4] = lv;
        }
        #pragma unroll
        for (int t = 0; t < 6; t++) {
            int e = tid + t * 256;
            int n = e >> 3;
            int q = e & 7;
            *(uint2*)&sBh[n * 40 + q * 4] =
                *(const uint2*)&g_wt_hi[(size_t)n * CC + k0 + q * 4];
            *(uint2*)&sBl[n * 40 + q * 4] =
                *(const uint2*)&g_wt_lo[(size_t)n * CC + k0 + q * 4];
        }
        __syncthreads();

        #pragma unroll
        for (int ks = 0; ks < 32; ks += 16) {
            uint32_t ah[2][4], al[2][4];
            #pragma unroll
            for (int mt = 0; mt < 2; mt++) {
                int r0 = (m0w + mt * 16 + g) * 40 + ks + tg * 2;
                int r1 = r0 + 8 * 40;
                ah[mt][0] = *(const uint32_t*)&sAh[r0];
                ah[mt][1] = *(const uint32_t*)&sAh[r1];
                ah[mt][2] = *(const uint32_t*)&sAh[r0 + 8];
                ah[mt][3] = *(const uint32_t*)&sAh[r1 + 8];
                al[mt][0] = *(const uint32_t*)&sAl[r0];
                al[mt][1] = *(const uint32_t*)&sAl[r1];
                al[mt][2] = *(const uint32_t*)&sAl[r0 + 8];
                al[mt][3] = *(const uint32_t*)&sAl[r1 + 8];
            }
            #pragma unroll
            for (int nt = 0; nt < 12; nt++) {
                int rb = (n0w + nt * 8 + g) * 40 + ks + tg * 2;
                uint32_t bh[2], bl[2];
                bh[0] = *(const uint32_t*)&sBh[rb];
                bh[1] = *(const uint32_t*)&sBh[rb + 8];
                bl[0] = *(const uint32_t*)&sBl[rb];
                bl[1] = *(const uint32_t*)&sBl[rb + 8];
                #pragma unroll
                for (int mt = 0; mt < 2; mt++) {
                    mma16816(acc[mt][nt], ah[mt], bh);
                    mma16816(acc[mt][nt], ah[mt], bl);
                    mma16816(acc[mt][nt], al[mt], bh);
                }
            }
        }
        __syncthreads();
    }

    // ---- epilogue ----
    const int b  = m0 >> 11;
    const int t0 = m0 & 2047;
    __nv_bfloat16* sTh = sb;               // [64][136] V^T hi staging
    __nv_bfloat16* sTl = sb + 64 * 136;    // [64][136] V^T lo

    #pragma unroll
    for (int nt = 0; nt < 12; nt++) {
        int nbase = n0w + nt * 8;
        #pragma unroll
        for (int mt = 0; mt < 2; mt++) {
            int row = m0w + mt * 16 + g;   // local 0..127
            float c0 = acc[mt][nt][0], c1 = acc[mt][nt][1];
            float c2 = acc[mt][nt][2], c3 = acc[mt][nt][3];
            if (nbase < 64) {
                c0 *= 0.125f; c1 *= 0.125f; c2 *= 0.125f; c3 *= 0.125f;
                size_t base0 = (size_t)(m0 + row) * HH + nbase + 2 * tg;
                size_t base1 = base0 + 8 * HH;
                *(uint32_t*)&g_qh[base0] = hi2(c0, c1);
                *(uint32_t*)&g_ql[base0] = lo2(c0, c1);
                *(uint32_t*)&g_qh[base1] = hi2(c2, c3);
                *(uint32_t*)&g_ql[base1] = lo2(c2, c3);
            } else if (nbase < 128) {
                size_t base0 = (size_t)(m0 + row) * HH + (nbase - 64) + 2 * tg;
                size_t base1 = base0 + 8 * HH;
                *(uint32_t*)&g_kh[base0] = hi2(c0, c1);
                *(uint32_t*)&g_kl[base0] = lo2(c0, c1);
                *(uint32_t*)&g_kh[base1] = hi2(c2, c3);
                *(uint32_t*)&g_kl[base1] = lo2(c2, c3);
            } else {
                int h = nbase - 128 + 2 * tg;
                __nv_bfloat16 h0 = __float2bfloat16(c0), h1 = __float2bfloat16(c1);
                __nv_bfloat16 h2 = __float2bfloat16(c2), h3 = __float2bfloat16(c3);
                sTh[h * 136 + row]           = h0;
                sTh[(h + 1) * 136 + row]     = h1;
                sTh[h * 136 + row + 8]       = h2;
                sTh[(h + 1) * 136 + row + 8] = h3;
                sTl[h * 136 + row]           = __float2bfloat16(c0 - __bfloat162float(h0));
                sTl[(h + 1) * 136 + row]     = __float2bfloat16(c1 - __bfloat162float(h1));
                sTl[h * 136 + row + 8]       = __float2bfloat16(c2 - __bfloat162float(h2));
                sTl[(h + 1) * 136 + row + 8] = __float2bfloat16(c3 - __bfloat162float(h3));
            }
        }
    }
    __syncthreads();
    // coalesced V^T copy: 64 h-rows x 128 t, hi+lo
    #pragma unroll
    for (int t = 0; t < 8; t++) {
        int e   = tid + t * 256;        // 0..2047
        int arr = e >> 10;
        int ee  = e & 1023;
        int h   = ee >> 4;
        int q   = ee & 15;
        uint4 v4 = *(const uint4*)&(arr ? sTl : sTh)[h * 136 + q * 8];
        __nv_bfloat16* dst = arr ? g_vtl : g_vth;
        *(uint4*)&dst[(size_t)(b * 64 + h) * 2048 + t0 + q * 8] = v4;
    }
}

// ---------------------------------------------------------------------------
// Attention on tensor cores.  BM=BN=64, 128 threads (4 warps x 16 q-rows).
// Persistent, 256 jobs heavy-first.  P stays in registers (C-frag == A-frag).
// smem (bf16, stride 72 = 144B rows, 16B-aligned, conflict-free frag LDS):
//   sQh@0 sQl@4608 sKh@9216 sKl@13824 sVh@18432 sVl@23040   (sV* = [h][kv])
// total 27648 bf16 = 55296 B
// ---------------------------------------------------------------------------
#define ATTN_CTAS 256
#define ATTN_SMEM 55296

__global__ __launch_bounds__(128, 1) void attn_mma_kernel(float* __restrict__ out)
{
    extern __shared__ __nv_bfloat16 sab[];
    __nv_bfloat16* sQh = sab;
    __nv_bfloat16* sQl = sab + 4608;
    __nv_bfloat16* sKh = sab + 9216;
    __nv_bfloat16* sKl = sab + 13824;
    __nv_bfloat16* sVh = sab + 18432;
    __nv_bfloat16* sVl = sab + 23040;

    __shared__ int sJob;

    const int tid  = threadIdx.x;
    const int wid  = tid >> 5;
    const int lane = tid & 31;
    const int g    = lane >> 2;
    const int tg   = lane & 3;
    const int rw   = wid * 16;           // warp's q-row base within tile

    for (;;) {
        if (tid == 0) sJob = atomicAdd(&g_ctr, 1);
        __syncthreads();
        const int job = sJob;
        if (job >= 256) break;

        const int qt = 31 - (job >> 3);  // heavy first
        const int b  = job & 7;
        const int q0 = qt * 64;

        // load Q tile (hi+lo): 64 rows x 64 bf16 each
        {
            const __nv_bfloat16* qh = g_qh + ((size_t)b * TT + q0) * HH;
            const __nv_bfloat16* ql = g_ql + ((size_t)b * TT + q0) * HH;
            #pragma unroll
            for (int t = 0; t < 4; t++) {
                int e = tid + t * 128;
                int m = e >> 3, q = e & 7;
                *(uint4*)&sQh[m * 72 + q * 8] = *(const uint4*)&qh[m * 64 + q * 8];
                *(uint4*)&sQl[m * 72 + q * 8] = *(const uint4*)&ql[m * 64 + q * 8];
            }
        }

        float m_i[2] = {-INFINITY, -INFINITY};
        float l_i[2] = {0.f, 0.f};
        float o[8][4];
        #pragma unroll
        for (int nt = 0; nt < 8; nt++)
            #pragma unroll
            for (int i = 0; i < 4; i++) o[nt][i] = 0.f;

        for (int t = 0; t <= qt; t++) {
            const int kv0 = t * 64;
            __syncthreads();   // prev chunk consumed (and Q visible on t=0)

            // K chunk [kv][h] and V^T chunk [h][kv]
            {
                const __nv_bfloat16* kh = g_kh + ((size_t)b * TT + kv0) * HH;
                const __nv_bfloat16* kl = g_kl + ((size_t)b * TT + kv0) * HH;
                #pragma unroll
                for (int tt = 0; tt < 4; tt++) {
                    int e = tid + tt * 128;
                    int m = e >> 3, q = e & 7;
                    *(uint4*)&sKh[m * 72 + q * 8] = *(const uint4*)&kh[m * 64 + q * 8];
                    *(uint4*)&sKl[m * 72 + q * 8] = *(const uint4*)&kl[m * 64 + q * 8];
                }
                #pragma unroll
                for (int tt = 0; tt < 4; tt++) {
                    int e = tid + tt * 128;
                    int h = e >> 3, q = e & 7;
                    size_t src = (size_t)(b * 64 + h) * 2048 + kv0 + q * 8;
                    *(uint4*)&sVh[h * 72 + q * 8] = *(const uint4*)&g_vth[src];
                    *(uint4*)&sVl[h * 72 + q * 8] = *(const uint4*)&g_vtl[src];
                }
            }
            __syncthreads();

            // ---- S = Q K^T (hi/lo split) ----
            float s[8][4];
            #pragma unroll
            for (int nt = 0; nt < 8; nt++)
                #pragma unroll
                for (int i = 0; i < 4; i++) s[nt][i] = 0.f;

            #pragma unroll
            for (int ks = 0; ks < 64; ks += 16) {
                uint32_t ah[4], al[4];
                int r0 = (rw + g) * 72 + ks + 2 * tg;
                int r1 = r0 + 8 * 72;
                ah[0] = *(const uint32_t*)&sQh[r0];
                ah[1] = *(const uint32_t*)&sQh[r1];
                ah[2] = *(const uint32_t*)&sQh[r0 + 8];
                ah[3] = *(const uint32_t*)&sQh[r1 + 8];
                al[0] = *(const uint32_t*)&sQl[r0];
                al[1] = *(const uint32_t*)&sQl[r1];
                al[2] = *(const uint32_t*)&sQl[r0 + 8];
                al[3] = *(const uint32_t*)&sQl[r1 + 8];
                #pragma unroll
                for (int nt = 0; nt < 8; nt++) {
                    int rb = (nt * 8 + g) * 72 + ks + 2 * tg;
                    uint32_t bh[2], bl[2];
                    bh[0] = *(const uint32_t*)&sKh[rb];
                    bh[1] = *(const uint32_t*)&sKh[rb + 8];
                    bl[0] = *(const uint32_t*)&sKl[rb];
                    bl[1] = *(const uint32_t*)&sKl[rb + 8];
                    mma16816(s[nt], ah, bh);
                    mma16816(s[nt], ah, bl);
                    mma16816(s[nt], al, bh);
                }
            }

            // ---- causal mask (diagonal chunk only; kv0 == q0 here) ----
            if (t == qt) {
                int r0 = rw + g;
                #pragma unroll
                for (int nt = 0; nt < 8; nt++) {
                    int c0 = nt * 8 + 2 * tg;
                    if (c0     > r0)     s[nt][0] = -INFINITY;
                    if (c0 + 1 > r0)     s[nt][1] = -INFINITY;
                    if (c0     > r0 + 8) s[nt][2] = -INFINITY;
                    if (c0 + 1 > r0 + 8) s[nt][3] = -INFINITY;
                }
            }

            // ---- online softmax (rows g and g+8; 4-lane shfl reduce) ----
            float mx0 = -INFINITY, mx1 = -INFINITY;
            #pragma unroll
            for (int nt = 0; nt < 8; nt++) {
                mx0 = fmaxf(mx0, fmaxf(s[nt][0], s[nt][1]));
                mx1 = fmaxf(mx1, fmaxf(s[nt][2], s[nt][3]));
            }
            mx0 = fmaxf(mx0, __shfl_xor_sync(0xffffffffu, mx0, 1));
            mx0 = fmaxf(mx0, __shfl_xor_sync(0xffffffffu, mx0, 2));
            mx1 = fmaxf(mx1, __shfl_xor_sync(0xffffffffu, mx1, 1));
            mx1 = fmaxf(mx1, __shfl_xor_sync(0xffffffffu, mx1, 2));

            float mn0 = fmaxf(m_i[0], mx0);
            float mn1 = fmaxf(m_i[1], mx1);
            float al0 = __expf(m_i[0] - mn0);
            float al1 = __expf(m_i[1] - mn1);
            float rs0 = 0.f, rs1 = 0.f;
            #pragma unroll
            for (int nt = 0; nt < 8; nt++) {
                s[nt][0] = __expf(s[nt][0] - mn0);
                s[nt][1] = __expf(s[nt][1] - mn0);
                s[nt][2] = __expf(s[nt][2] - mn1);
                s[nt][3] = __expf(s[nt][3] - mn1);
                rs0 += s[nt][0] + s[nt][1];
                rs1 += s[nt][2] + s[nt][3];
            }
            rs0 += __shfl_xor_sync(0xffffffffu, rs0, 1);
            rs0 += __shfl_xor_sync(0xffffffffu, rs0, 2);
            rs1 += __shfl_xor_sync(0xffffffffu, rs1, 1);
            rs1 += __shfl_xor_sync(0xffffffffu, rs1, 2);
            l_i[0] = l_i[0] * al0 + rs0;
            l_i[1] = l_i[1] * al1 + rs1;
            m_i[0] = mn0;
            m_i[1] = mn1;
            #pragma unroll
            for (int nt = 0; nt < 8; nt++) {
                o[nt][0] *= al0; o[nt][1] *= al0;
                o[nt][2] *= al1; o[nt][3] *= al1;
            }

            // ---- O += P V (P in registers: C-frag layout == A-frag layout) ----
            #pragma unroll
            for (int kk = 0; kk < 4; kk++) {
                int j0 = 2 * kk;
                uint32_t ph[4], pl[4];
                ph[0] = hi2(s[j0][0],     s[j0][1]);
                ph[1] = hi2(s[j0][2],     s[j0][3]);
                ph[2] = hi2(s[j0 + 1][0], s[j0 + 1][1]);
                ph[3] = hi2(s[j0 + 1][2], s[j0 + 1][3]);
                pl[0] = lo2(s[j0][0],     s[j0][1]);
                pl[1] = lo2(s[j0][2],     s[j0][3]);
                pl[2] = lo2(s[j0 + 1][0], s[j0 + 1][1]);
                pl[3] = lo2(s[j0 + 1][2], s[j0 + 1][3]);
                #pragma unroll
                for (int nt = 0; nt < 8; nt++) {
                    int rb = (nt * 8 + g) * 72 + kk * 16 + 2 * tg;
                    uint32_t bvh[2], bvl[2];
                    bvh[0] = *(const uint32_t*)&sVh[rb];
                    bvh[1] = *(const uint32_t*)&sVh[rb + 8];
                    bvl[0] = *(const uint32_t*)&sVl[rb];
                    bvl[1] = *(const uint32_t*)&sVl[rb + 8];
                    mma16816(o[nt], ph, bvh);
                    mma16816(o[nt], ph, bvl);
                    mma16816(o[nt], pl, bvh);
                }
            }
        }

        // ---- epilogue ----
        float inv0 = 1.f / l_i[0];
        float inv1 = 1.f / l_i[1];
        int row0 = q0 + rw + g;
        #pragma unroll
        for (int nt = 0; nt < 8; nt++) {
            *(float2*)&out[((size_t)b * TT + row0) * HH + nt * 8 + 2 * tg] =
                make_float2(o[nt][0] * inv0, o[nt][1] * inv0);
            *(float2*)&out[((size_t)b * TT + row0 + 8) * HH + nt * 8 + 2 * tg] =
                make_float2(o[nt][2] * inv1, o[nt][3] * inv1);
        }
    }

    if (tid == 0) {
        if (atomicAdd(&g_done, 1) == ATTN_CTAS - 1) {
            g_ctr  = 0;
            g_done = 0;
        }
    }
}

extern "C" void kernel_launch(void* const* d_in, const int* in_sizes, int n_in,
                              void* d_out, int out_size)
{
    const float* x  = (const float*)d_in[0];
    const float* Wq = (const float*)d_in[1];
    const float* Wk = (const float*)d_in[2];
    const float* Wv = (const float*)d_in[3];
    float* out = (float*)d_out;

    cudaFuncSetAttribute(proj_mma_kernel,
                         cudaFuncAttributeMaxDynamicSharedMemorySize, PROJ_SMEM);
    cudaFuncSetAttribute(attn_mma_kernel,
                         cudaFuncAttributeMaxDynamicSharedMemorySize, ATTN_SMEM);

    wprep_kernel<<<192, 256>>>(Wq, Wk, Wv);
    proj_mma_kernel<<<BB * TT / 128, 256, PROJ_SMEM>>>(x);
    attn_mma_kernel<<<ATTN_CTAS, 128, ATTN_SMEM>>>(out);
}

// round 9
// speedup vs baseline: 2.7583x; 1.0462x over previous
#include <cuda_runtime.h>
#include <cuda_bf16.h>
#include <math.h>
#include <cstdint>

#define BB 8
#define TT 2048
#define CC 1024
#define HH 64

// bf16 hi/lo tensors
__device__ __nv_bfloat16 g_xh[BB*TT*CC], g_xl[BB*TT*CC];   // x  [m][c]
__device__ __nv_bfloat16 g_qh[BB*TT*HH], g_ql[BB*TT*HH];   // q  [b][t][h] (pre-scaled)
__device__ __nv_bfloat16 g_kh[BB*TT*HH], g_kl[BB*TT*HH];   // k  [b][t][h]
__device__ __nv_bfloat16 g_vth[BB*HH*TT], g_vtl[BB*HH*TT]; // v^T [b][h][t]
__device__ __nv_bfloat16 g_wt_hi[192*CC];                  // W^T [n][k], n = mat*64+h
__device__ __nv_bfloat16 g_wt_lo[192*CC];
__device__ int g_ctr  = 0;
__device__ int g_done = 0;

// ---- mma.sync m16n8k16 bf16 (sm_80 baseline) ----
__device__ __forceinline__ void mma16816(float* c, const uint32_t* a, const uint32_t* b) {
    asm volatile(
        "mma.sync.aligned.m16n8k16.row.col.f32.bf16.bf16.f32 "
        "{%0,%1,%2,%3}, {%4,%5,%6,%7}, {%8,%9}, {%0,%1,%2,%3};"
        : "+f"(c[0]), "+f"(c[1]), "+f"(c[2]), "+f"(c[3])
        : "r"(a[0]), "r"(a[1]), "r"(a[2]), "r"(a[3]), "r"(b[0]), "r"(b[1]));
}
// ---- ldmatrix x4 (sm_75 baseline) ----
__device__ __forceinline__ void ldsm4(uint32_t* r, uint32_t addr) {
    asm volatile("ldmatrix.sync.aligned.m8n8.x4.shared.b16 {%0,%1,%2,%3}, [%4];"
        : "=r"(r[0]), "=r"(r[1]), "=r"(r[2]), "=r"(r[3]) : "r"(addr) : "memory");
}
// ---- cp.async (sm_80 baseline) ----
#define CP16(dst, src) asm volatile("cp.async.cg.shared.global [%0], [%1], 16;" :: "r"(dst), "l"(src) : "memory")
#define CP_COMMIT()    asm volatile("cp.async.commit_group;" ::: "memory")
#define CP_WAIT1()     asm volatile("cp.async.wait_group 1;" ::: "memory")

__device__ __forceinline__ uint32_t smem_u32(const void* p) {
    uint32_t a;
    asm("{ .reg .u64 t; cvta.to.shared.u64 t, %1; cvt.u32.u64 %0, t; }" : "=r"(a) : "l"(p));
    return a;
}
__device__ __forceinline__ uint32_t hi2(float a, float b) {
    return ((uint32_t)__bfloat16_as_ushort(__float2bfloat16(b)) << 16) |
           (uint32_t)__bfloat16_as_ushort(__float2bfloat16(a));
}
__device__ __forceinline__ uint32_t lo2(float a, float b) {
    float ra = a - __bfloat162float(__float2bfloat16(a));
    float rb = b - __bfloat162float(__float2bfloat16(b));
    return hi2(ra, rb);
}

// ---------------------------------------------------------------------------
// Prep kernels: W^T hi/lo and x hi/lo.
// ---------------------------------------------------------------------------
__global__ __launch_bounds__(256) void wprep_kernel(
    const float* __restrict__ Wq, const float* __restrict__ Wk,
    const float* __restrict__ Wv)
{
    int n = blockIdx.x;                 // 0..191
    const float* W = (n < 64) ? Wq : (n < 128) ? Wk : Wv;
    int h = n & 63;
    for (int k = threadIdx.x; k < CC; k += 256) {
        float v = W[(size_t)k * HH + h];
        __nv_bfloat16 hi = __float2bfloat16(v);
        g_wt_hi[(size_t)n * CC + k] = hi;
        g_wt_lo[(size_t)n * CC + k] = __float2bfloat16(v - __bfloat162float(hi));
    }
}

__global__ __launch_bounds__(256) void xprep_kernel(const float* __restrict__ x)
{
    const int stride = gridDim.x * blockDim.x;
    for (int i = blockIdx.x * blockDim.x + threadIdx.x; i < BB*TT*CC/4; i += stride) {
        float4 v = *(const float4*)&x[(size_t)i * 4];
        uint2 hv, lv;
        hv.x = hi2(v.x, v.y);  hv.y = hi2(v.z, v.w);
        lv.x = lo2(v.x, v.y);  lv.y = lo2(v.z, v.w);
        *(uint2*)&g_xh[(size_t)i * 4] = hv;
        *(uint2*)&g_xl[(size_t)i * 4] = lv;
    }
}

// ---------------------------------------------------------------------------
// Projection GEMM: cp.async double-buffered, ldmatrix fragments.
// 128 CTAs x 256 thr (8 warps: 4M x 2N; warp tile 32m x 96n).  K chunks of 32.
// smem per stage (bf16, stride 40): Ah@0(5120) Al@5120 Bh@10240(7680) Bl@17920
// stage stride 25600;  2 stages = 51200 bf16 = 102400 B
// ---------------------------------------------------------------------------
#define PROJ_SMEM 102400
#define PSS 25600

__global__ __launch_bounds__(256, 1) void proj_mma_kernel()
{
    extern __shared__ __nv_bfloat16 sb[];
    const uint32_t sbase = smem_u32(sb);

    const int tid  = threadIdx.x;
    const int wid  = tid >> 5;
    const int lane = tid & 31;
    const int g    = lane >> 2;
    const int tg   = lane & 3;
    const int m0   = blockIdx.x * 128;
    const int m0w  = (wid >> 1) * 32;
    const int n0w  = (wid & 1) * 96;

    // ldmatrix per-lane offsets
    const int m_off = (lane & 7) + ((lane >> 3) & 1) * 8;
    const int kA    = (lane >> 4) * 8;
    const int n_off = (lane & 7) + ((lane >> 4) & 1) * 8;
    const int kB    = ((lane >> 3) & 1) * 8;

    auto issue_chunk = [&](int kc, int s) {
        const int k0 = kc * 32;
        const uint32_t st = sbase + 2 * (s * PSS);
        #pragma unroll
        for (int t = 0; t < 4; t++) {            // A: 1024 x 16B (rows of 32 bf16)
            int e = tid + t * 256;
            int arr = e >> 9;
            int ee  = e & 511;
            int row = ee >> 2, q = ee & 3;
            const __nv_bfloat16* src =
                (arr ? g_xl : g_xh) + (size_t)(m0 + row) * CC + k0 + q * 8;
            CP16(st + 2 * (arr * 5120 + row * 40 + q * 8), src);
        }
        #pragma unroll
        for (int t = 0; t < 6; t++) {            // B: 1536 x 16B
            int e = tid + t * 256;
            int arr = (e >= 768);
            int ee  = arr ? e - 768 : e;
            int row = ee >> 2, q = ee & 3;
            const __nv_bfloat16* src =
                (arr ? g_wt_lo : g_wt_hi) + (size_t)row * CC + k0 + q * 8;
            CP16(st + 2 * (10240 + arr * 7680 + row * 40 + q * 8), src);
        }
    };

    float acc[2][12][4];
    #pragma unroll
    for (int mt = 0; mt < 2; mt++)
        #pragma unroll
        for (int nt = 0; nt < 12; nt++)
            #pragma unroll
            for (int i = 0; i < 4; i++) acc[mt][nt][i] = 0.f;

    issue_chunk(0, 0); CP_COMMIT();
    issue_chunk(1, 1); CP_COMMIT();

    for (int kc = 0; kc < 32; kc++) {
        const int s = kc & 1;
        CP_WAIT1();
        __syncthreads();

        const uint32_t ah_b = sbase + 2 * (s * PSS);
        const uint32_t al_b = ah_b + 2 * 5120;
        const uint32_t bh_b = ah_b + 2 * 10240;
        const uint32_t bl_b = ah_b + 2 * 17920;

        #pragma unroll
        for (int ks = 0; ks < 32; ks += 16) {
            uint32_t ah[2][4], al[2][4];
            #pragma unroll
            for (int mt = 0; mt < 2; mt++) {
                int ro = (m0w + mt * 16 + m_off) * 40 + ks + kA;
                ldsm4(ah[mt], ah_b + 2 * ro);
                ldsm4(al[mt], al_b + 2 * ro);
            }
            #pragma unroll
            for (int p = 0; p < 6; p++) {
                int ro = (n0w + p * 16 + n_off) * 40 + ks + kB;
                uint32_t bh[4], bl[4];
                ldsm4(bh, bh_b + 2 * ro);
                ldsm4(bl, bl_b + 2 * ro);
                #pragma unroll
                for (int hf = 0; hf < 2; hf++) {
                    int nt = p * 2 + hf;
                    #pragma unroll
                    for (int mt = 0; mt < 2; mt++) {
                        mma16816(acc[mt][nt], ah[mt], bh + hf * 2);
                        mma16816(acc[mt][nt], ah[mt], bl + hf * 2);
                        mma16816(acc[mt][nt], al[mt], bh + hf * 2);
                    }
                }
            }
        }
        __syncthreads();
        if (kc + 2 < 32) issue_chunk(kc + 2, s);
        CP_COMMIT();
    }

    // ---- epilogue: Q (x0.125) / K -> [t][h] hi/lo;  V -> transpose [h][t] ----
    const int b  = m0 >> 11;
    const int t0 = m0 & 2047;
    __nv_bfloat16* sTh = sb;               // [64][136]
    __nv_bfloat16* sTl = sb + 64 * 136;

    #pragma unroll
    for (int nt = 0; nt < 12; nt++) {
        int nbase = n0w + nt * 8;
        #pragma unroll
        for (int mt = 0; mt < 2; mt++) {
            int row = m0w + mt * 16 + g;
            float c0 = acc[mt][nt][0], c1 = acc[mt][nt][1];
            float c2 = acc[mt][nt][2], c3 = acc[mt][nt][3];
            if (nbase < 64) {
                c0 *= 0.125f; c1 *= 0.125f; c2 *= 0.125f; c3 *= 0.125f;
                size_t base0 = (size_t)(m0 + row) * HH + nbase + 2 * tg;
                size_t base1 = base0 + 8 * HH;
                *(uint32_t*)&g_qh[base0] = hi2(c0, c1);
                *(uint32_t*)&g_ql[base0] = lo2(c0, c1);
                *(uint32_t*)&g_qh[base1] = hi2(c2, c3);
                *(uint32_t*)&g_ql[base1] = lo2(c2, c3);
            } else if (nbase < 128) {
                size_t base0 = (size_t)(m0 + row) * HH + (nbase - 64) + 2 * tg;
                size_t base1 = base0 + 8 * HH;
                *(uint32_t*)&g_kh[base0] = hi2(c0, c1);
                *(uint32_t*)&g_kl[base0] = lo2(c0, c1);
                *(uint32_t*)&g_kh[base1] = hi2(c2, c3);
                *(uint32_t*)&g_kl[base1] = lo2(c2, c3);
            } else {
                int h = nbase - 128 + 2 * tg;
                __nv_bfloat16 h0 = __float2bfloat16(c0), h1 = __float2bfloat16(c1);
                __nv_bfloat16 h2 = __float2bfloat16(c2), h3 = __float2bfloat16(c3);
                sTh[h * 136 + row]           = h0;
                sTh[(h + 1) * 136 + row]     = h1;
                sTh[h * 136 + row + 8]       = h2;
                sTh[(h + 1) * 136 + row + 8] = h3;
                sTl[h * 136 + row]           = __float2bfloat16(c0 - __bfloat162float(h0));
                sTl[(h + 1) * 136 + row]     = __float2bfloat16(c1 - __bfloat162float(h1));
                sTl[h * 136 + row + 8]       = __float2bfloat16(c2 - __bfloat162float(h2));
                sTl[(h + 1) * 136 + row + 8] = __float2bfloat16(c3 - __bfloat162float(h3));
            }
        }
    }
    __syncthreads();
    #pragma unroll
    for (int t = 0; t < 8; t++) {
        int e   = tid + t * 256;
        int arr = e >> 10;
        int ee  = e & 1023;
        int h   = ee >> 4;
        int q   = ee & 15;
        uint4 v4 = *(const uint4*)&(arr ? sTl : sTh)[h * 136 + q * 8];
        __nv_bfloat16* dst = arr ? g_vtl : g_vth;
        *(uint4*)&dst[(size_t)(b * 64 + h) * 2048 + t0 + q * 8] = v4;
    }
}

// ---------------------------------------------------------------------------
// Attention: cp.async double-buffered K/V, ldmatrix fragments, P in registers.
// BM=BN=64, 128 threads (4 warps x 16 q-rows), 256 persistent jobs heavy-first.
// smem (bf16, stride 72): Qh@0(4608) Ql@4608; stage s @9216+s*18432:
//   Kh+0 Kl+4608 Vh+9216 Vl+13824.   total 46080 bf16 = 92160 B
// Rows are 64 bf16 = 128 B = 8 x 16B transfers -> loaders use >>3 / &7.
// ---------------------------------------------------------------------------
#define ATTN_CTAS 256
#define ATTN_SMEM 92160

__global__ __launch_bounds__(128, 1) void attn_mma_kernel(float* __restrict__ out)
{
    extern __shared__ __nv_bfloat16 sab[];
    const uint32_t sbase = smem_u32(sab);
    __shared__ int sJob;

    const int tid  = threadIdx.x;
    const int wid  = tid >> 5;
    const int lane = tid & 31;
    const int g    = lane >> 2;
    const int tg   = lane & 3;
    const int rw   = wid * 16;

    const int m_off = (lane & 7) + ((lane >> 3) & 1) * 8;
    const int kA    = (lane >> 4) * 8;
    const int n_off = (lane & 7) + ((lane >> 4) & 1) * 8;
    const int kB    = ((lane >> 3) & 1) * 8;

    for (;;) {
        if (tid == 0) sJob = atomicAdd(&g_ctr, 1);
        __syncthreads();
        const int job = sJob;
        if (job >= 256) break;

        const int qt = 31 - (job >> 3);
        const int b  = job & 7;
        const int q0 = qt * 64;

        auto issue_kv = [&](int t, int s) {
            const int kv0 = t * 64;
            const uint32_t st = sbase + 2 * (9216 + s * 18432);
            // 4 arrays x 64 rows x 8 x 16B = 2048 transfers
            #pragma unroll
            for (int tt = 0; tt < 16; tt++) {
                int e = tid + tt * 128;
                int arr = e >> 9;            // 0:Kh 1:Kl 2:Vh 3:Vl
                int ee  = e & 511;
                int row = ee >> 3, q = ee & 7;
                const __nv_bfloat16* src;
                if (arr == 0)      src = g_kh  + ((size_t)b * TT + kv0 + row) * HH + q * 8;
                else if (arr == 1) src = g_kl  + ((size_t)b * TT + kv0 + row) * HH + q * 8;
                else if (arr == 2) src = g_vth + ((size_t)(b * 64 + row)) * 2048 + kv0 + q * 8;
                else               src = g_vtl + ((size_t)(b * 64 + row)) * 2048 + kv0 + q * 8;
                CP16(st + 2 * (arr * 4608 + row * 72 + q * 8), src);
            }
        };

        // group 0: Q (2 arrays x 64 rows x 8 x 16B = 1024 transfers) + KV chunk 0
        #pragma unroll
        for (int tt = 0; tt < 8; tt++) {
            int e = tid + tt * 128;
            int arr = e >> 9;
            int ee  = e & 511;
            int row = ee >> 3, q = ee & 7;
            const __nv_bfloat16* src =
                (arr ? g_ql : g_qh) + ((size_t)b * TT + q0 + row) * HH + q * 8;
            CP16(sbase + 2 * (arr * 4608 + row * 72 + q * 8), src);
        }
        issue_kv(0, 0); CP_COMMIT();
        if (qt >= 1) issue_kv(1, 1);
        CP_COMMIT();

        float m_i[2] = {-INFINITY, -INFINITY};
        float l_i[2] = {0.f, 0.f};
        float o[8][4];
        #pragma unroll
        for (int nt = 0; nt < 8; nt++)
            #pragma unroll
            for (int i = 0; i < 4; i++) o[nt][i] = 0.f;

        for (int t = 0; t <= qt; t++) {
            const int s = t & 1;
            CP_WAIT1();
            __syncthreads();

            const uint32_t kh_b = sbase + 2 * (9216 + s * 18432);
            const uint32_t kl_b = kh_b + 2 * 4608;
            const uint32_t vh_b = kh_b + 2 * 9216;
            const uint32_t vl_b = kh_b + 2 * 13824;
            const uint32_t qh_b = sbase;
            const uint32_t ql_b = sbase + 2 * 4608;

            // ---- S = Q K^T ----
            float sc[8][4];
            #pragma unroll
            for (int nt = 0; nt < 8; nt++)
                #pragma unroll
                for (int i = 0; i < 4; i++) sc[nt][i] = 0.f;

            #pragma unroll
            for (int ks = 0; ks < 64; ks += 16) {
                uint32_t ah[4], al[4];
                int ro = (rw + m_off) * 72 + ks + kA;
                ldsm4(ah, qh_b + 2 * ro);
                ldsm4(al, ql_b + 2 * ro);
                #pragma unroll
                for (int p = 0; p < 4; p++) {
                    int rb = (p * 16 + n_off) * 72 + ks + kB;
                    uint32_t bh[4], bl[4];
                    ldsm4(bh, kh_b + 2 * rb);
                    ldsm4(bl, kl_b + 2 * rb);
                    #pragma unroll
                    for (int hf = 0; hf < 2; hf++) {
                        int nt = p * 2 + hf;
                        mma16816(sc[nt], ah, bh + hf * 2);
                        mma16816(sc[nt], ah, bl + hf * 2);
                        mma16816(sc[nt], al, bh + hf * 2);
                    }
                }
            }

            // ---- causal mask (diagonal chunk) ----
            if (t == qt) {
                int r0 = rw + g;
                #pragma unroll
                for (int nt = 0; nt < 8; nt++) {
                    int c0 = nt * 8 + 2 * tg;
                    if (c0     > r0)     sc[nt][0] = -INFINITY;
                    if (c0 + 1 > r0)     sc[nt][1] = -INFINITY;
                    if (c0     > r0 + 8) sc[nt][2] = -INFINITY;
                    if (c0 + 1 > r0 + 8) sc[nt][3] = -INFINITY;
                }
            }

            // ---- online softmax ----
            float mx0 = -INFINITY, mx1 = -INFINITY;
            #pragma unroll
            for (int nt = 0; nt < 8; nt++) {
                mx0 = fmaxf(mx0, fmaxf(sc[nt][0], sc[nt][1]));
                mx1 = fmaxf(mx1, fmaxf(sc[nt][2], sc[nt][3]));
            }
            mx0 = fmaxf(mx0, __shfl_xor_sync(0xffffffffu, mx0, 1));
            mx0 = fmaxf(mx0, __shfl_xor_sync(0xffffffffu, mx0, 2));
            mx1 = fmaxf(mx1, __shfl_xor_sync(0xffffffffu, mx1, 1));
            mx1 = fmaxf(mx1, __shfl_xor_sync(0xffffffffu, mx1, 2));

            float mn0 = fmaxf(m_i[0], mx0);
            float mn1 = fmaxf(m_i[1], mx1);
            float al0 = __expf(m_i[0] - mn0);
            float al1 = __expf(m_i[1] - mn1);
            float rs0 = 0.f, rs1 = 0.f;
            #pragma unroll
            for (int nt = 0; nt < 8; nt++) {
                sc[nt][0] = __expf(sc[nt][0] - mn0);
                sc[nt][1] = __expf(sc[nt][1] - mn0);
                sc[nt][2] = __expf(sc[nt][2] - mn1);
                sc[nt][3] = __expf(sc[nt][3] - mn1);
                rs0 += sc[nt][0] + sc[nt][1];
                rs1 += sc[nt][2] + sc[nt][3];
            }
            rs0 += __shfl_xor_sync(0xffffffffu, rs0, 1);
            rs0 += __shfl_xor_sync(0xffffffffu, rs0, 2);
            rs1 += __shfl_xor_sync(0xffffffffu, rs1, 1);
            rs1 += __shfl_xor_sync(0xffffffffu, rs1, 2);
            l_i[0] = l_i[0] * al0 + rs0;
            l_i[1] = l_i[1] * al1 + rs1;
            m_i[0] = mn0;
            m_i[1] = mn1;
            #pragma unroll
            for (int nt = 0; nt < 8; nt++) {
                o[nt][0] *= al0; o[nt][1] *= al0;
                o[nt][2] *= al1; o[nt][3] *= al1;
            }

            // ---- O += P V ----
            #pragma unroll
            for (int kk = 0; kk < 4; kk++) {
                int j0 = 2 * kk;
                uint32_t ph[4], pl[4];
                ph[0] = hi2(sc[j0][0],     sc[j0][1]);
                ph[1] = hi2(sc[j0][2],     sc[j0][3]);
                ph[2] = hi2(sc[j0 + 1][0], sc[j0 + 1][1]);
                ph[3] = hi2(sc[j0 + 1][2], sc[j0 + 1][3]);
                pl[0] = lo2(sc[j0][0],     sc[j0][1]);
                pl[1] = lo2(sc[j0][2],     sc[j0][3]);
                pl[2] = lo2(sc[j0 + 1][0], sc[j0 + 1][1]);
                pl[3] = lo2(sc[j0 + 1][2], sc[j0 + 1][3]);
                #pragma unroll
                for (int p = 0; p < 4; p++) {
                    int rb = (p * 16 + n_off) * 72 + kk * 16 + kB;
                    uint32_t bvh[4], bvl[4];
                    ldsm4(bvh, vh_b + 2 * rb);
                    ldsm4(bvl, vl_b + 2 * rb);
                    #pragma unroll
                    for (int hf = 0; hf < 2; hf++) {
                        int nt = p * 2 + hf;
                        mma16816(o[nt], ph, bvh + hf * 2);
                        mma16816(o[nt], ph, bvl + hf * 2);
                        mma16816(o[nt], pl, bvh + hf * 2);
                    }
                }
            }

            __syncthreads();
            if (t + 2 <= qt) issue_kv(t + 2, s);
            CP_COMMIT();
        }

        // ---- epilogue ----
        float inv0 = 1.f / l_i[0];
        float inv1 = 1.f / l_i[1];
        int row0 = q0 + rw + g;
        #pragma unroll
        for (int nt = 0; nt < 8; nt++) {
            *(float2*)&out[((size_t)b * TT + row0) * HH + nt * 8 + 2 * tg] =
                make_float2(o[nt][0] * inv0, o[nt][1] * inv0);
            *(float2*)&out[((size_t)b * TT + row0 + 8) * HH + nt * 8 + 2 * tg] =
                make_float2(o[nt][2] * inv1, o[nt][3] * inv1);
        }
    }

    if (tid == 0) {
        if (atomicAdd(&g_done, 1) == ATTN_CTAS - 1) {
            g_ctr  = 0;
            g_done = 0;
        }
    }
}

extern "C" void kernel_launch(void* const* d_in, const int* in_sizes, int n_in,
                              void* d_out, int out_size)
{
    const float* x  = (const float*)d_in[0];
    const float* Wq = (const float*)d_in[1];
    const float* Wk = (const float*)d_in[2];
    const float* Wv = (const float*)d_in[3];
    float* out = (float*)d_out;

    cudaFuncSetAttribute(proj_mma_kernel,
                         cudaFuncAttributeMaxDynamicSharedMemorySize, PROJ_SMEM);
    cudaFuncSetAttribute(attn_mma_kernel,
                         cudaFuncAttributeMaxDynamicSharedMemorySize, ATTN_SMEM);

    wprep_kernel<<<192, 256>>>(Wq, Wk, Wv);
    xprep_kernel<<<2048, 256>>>(x);
    proj_mma_kernel<<<BB * TT / 128, 256, PROJ_SMEM>>>();
    attn_mma_kernel<<<ATTN_CTAS, 128, ATTN_SMEM>>>(out);
}